// round 15
// baseline (speedup 1.0000x reference)
#include <cuda_runtime.h>
#include <cuda_bf16.h>
#include <math.h>
#include <stdint.h>

#define BB   8
#define CIN  64
#define COUT 64
#define HH   128
#define WW   128
#define HID  8
#define HW   (HH*WW)

// ---------------------------------------------------------------------------
// Device scratch
// ---------------------------------------------------------------------------
__device__ float g_pooled[BB*CIN*9];
// bf16 B tiles for mma: slab = (b*9+j)*2+split, layout [n=128][kk=64] bf16
__device__ __align__(16) unsigned char g_kbf[(size_t)BB*9*2*16384];
__device__ float g_sa[BB*HW];
__device__ float g_pmin[BB*16];
__device__ float g_pmax[BB*16];

// ---------------------------------------------------------------------------
// 1) pool + sa (proven kernel, unchanged)
// ---------------------------------------------------------------------------
__global__ __launch_bounds__(256) void poolsa_kernel(const float* __restrict__ feat,
                                                     const float* __restrict__ pred,
                                                     const float* __restrict__ gk) {
    const int bid = blockIdx.x, tid = threadIdx.x;
    if (bid < 512) {
        __shared__ float red[9][256];
        const float* src = feat + (size_t)bid * HW;
        float a[9];
        #pragma unroll
        for (int i = 0; i < 9; ++i) a[i] = 0.f;
        for (int idx = tid; idx < HW; idx += 256) {
            float v = src[idx];
            int y = idx >> 7, x = idx & 127;
            bool rm0 = (y < 43), rm1 = (y >= 42) & (y < 86), rm2 = (y >= 85);
            bool cm0 = (x < 43), cm1 = (x >= 42) & (x < 86), cm2 = (x >= 85);
            if (rm0) { if (cm0) a[0]+=v; if (cm1) a[1]+=v; if (cm2) a[2]+=v; }
            if (rm1) { if (cm0) a[3]+=v; if (cm1) a[4]+=v; if (cm2) a[5]+=v; }
            if (rm2) { if (cm0) a[6]+=v; if (cm1) a[7]+=v; if (cm2) a[8]+=v; }
        }
        #pragma unroll
        for (int k = 0; k < 9; ++k) red[k][tid] = a[k];
        __syncthreads();
        for (int s = 128; s > 0; s >>= 1) {
            if (tid < s) {
                #pragma unroll
                for (int k = 0; k < 9; ++k) red[k][tid] += red[k][tid + s];
            }
            __syncthreads();
        }
        if (tid < 9) {
            const float cnt[3] = {43.f, 44.f, 43.f};
            g_pooled[bid*9 + tid] = red[tid][0] / (cnt[tid/3] * cnt[tid%3]);
        }
    } else {
        __shared__ float sp[46][46];
        __shared__ float sg[225];
        __shared__ float rmn[8], rmx[8];
        const int t = bid - 512, b = t >> 4, rem = t & 15;
        const int y0 = (rem >> 2) * 32, x0 = (rem & 3) * 32;
        for (int i = tid; i < 225; i += 256) sg[i] = gk[i];
        for (int i = tid; i < 46*46; i += 256) {
            int ly = i / 46, lx = i % 46;
            int gy = y0 - 7 + ly, gx = x0 - 7 + lx;
            float v = 0.f;
            if ((unsigned)gy < 128u && (unsigned)gx < 128u)
                v = 1.f / (1.f + expf(-pred[b*HW + gy*128 + gx]));
            sp[ly][lx] = v;
        }
        __syncthreads();
        float tmn = 3.4e38f, tmx = 0.f;
        #pragma unroll
        for (int p = 0; p < 4; ++p) {
            int id = tid + p*256, py = id >> 5, px = id & 31;
            float s = 0.f;
            for (int u = 0; u < 15; ++u)
                #pragma unroll
                for (int v = 0; v < 15; ++v)
                    s += sp[py + u][px + v] * sg[u*15 + v];
            g_sa[b*HW + (y0 + py)*128 + (x0 + px)] = s;
            tmn = fminf(tmn, s); tmx = fmaxf(tmx, s);
        }
        #pragma unroll
        for (int o = 16; o; o >>= 1) {
            tmn = fminf(tmn, __shfl_xor_sync(0xffffffffu, tmn, o));
            tmx = fmaxf(tmx, __shfl_xor_sync(0xffffffffu, tmx, o));
        }
        if ((tid & 31) == 0) { rmn[tid >> 5] = tmn; rmx[tid >> 5] = tmx; }
        __syncthreads();
        if (tid == 0) {
            #pragma unroll
            for (int w = 0; w < 8; ++w) { tmn = fminf(tmn, rmn[w]); tmx = fmaxf(tmx, rmx[w]); }
            g_pmin[b*16 + (y0 >> 5)*4 + (x0 >> 5)] = tmn;
            g_pmax[b*16 + (y0 >> 5)*4 + (x0 >> 5)] = tmx;
        }
    }
}

// ---------------------------------------------------------------------------
// 2) kerngen: MLP + emit bf16 hi/lo B tiles [n=r*64+co][kk] per K-chunk slab
// ---------------------------------------------------------------------------
__global__ void kerngen_kernel(const float* __restrict__ w1,
                               const float* __restrict__ b1,
                               const float* __restrict__ w2,
                               const float* __restrict__ b2) {
    const int blk = blockIdx.x;               // 0..143 = (b, r, yx)
    const int b = blk / 18, rem = blk % 18;
    const int r = rem / 9, yx = rem % 9;
    __shared__ float hs[8];
    if (threadIdx.x < 8) {
        const int c = r*8 + threadIdx.x;
        float v = b1[c];
        #pragma unroll 8
        for (int ci = 0; ci < CIN; ++ci)
            v += w1[c*CIN + ci] * g_pooled[(b*CIN + ci)*9 + yx];
        hs[threadIdx.x] = 1.f / (1.f + expf(-v));
    }
    __syncthreads();
    for (int idx = threadIdx.x; idx < CIN*COUT; idx += 256) {
        const int co = idx & 63, ci = idx >> 6;
        const int q = r*(CIN*COUT) + co*CIN + ci;
        const float* wp = w2 + (size_t)q * HID;
        float v = b2[q];
        #pragma unroll
        for (int h = 0; h < HID; ++h) v += wp[h] * hs[h];
        __nv_bfloat16 hi = __float2bfloat16(v);
        __nv_bfloat16 lo = __float2bfloat16(v - __bfloat162float(hi));
        int K = ci*9 + yx, j = K >> 6, kk = K & 63;
        int n = r*64 + co;
        size_t base = ((size_t)((b*9 + j)*2))*16384 + (size_t)n*128 + kk*2;
        *(unsigned short*)(g_kbf + base)         = __bfloat16_as_ushort(hi);
        *(unsigned short*)(g_kbf + base + 16384) = __bfloat16_as_ushort(lo);
    }
}

// ---------------------------------------------------------------------------
// 3) conv: mma.sync bf16 3-term implicit GEMM, pipelined chunk loop.
//    Block=(y,b), 256 thr, 8 warps (4x2). D[128px,128n], K=576 in 9 chunks.
//    fc double-buffered: chunk j+1's fcache prefetched during compute of j;
//    B load overlapped with A-build.
//    dsm: A_hi A_lo B_hi B_lo (144B rows) | fc[2] fp32 [8][3][132]
// ---------------------------------------------------------------------------
#define A_HI 0u
#define A_LO 18432u
#define B_HI 36864u
#define B_LO 55296u
#define FC_OFF 73728u
#define FC_SZ  12672u
#define CONV_DSMEM 99072

extern __shared__ __align__(16) unsigned char dsm[];

#define LDSM4(r0,r1,r2,r3,a) \
    asm volatile("ldmatrix.sync.aligned.m8n8.x4.shared.b16 {%0,%1,%2,%3},[%4];" \
        : "=r"(r0),"=r"(r1),"=r"(r2),"=r"(r3) : "r"(a))

#define MMA(d, a, b0, b1)                                                       \
    asm volatile("mma.sync.aligned.m16n8k16.row.col.f32.bf16.bf16.f32 "         \
        "{%0,%1,%2,%3},{%4,%5,%6,%7},{%8,%9},{%0,%1,%2,%3};"                    \
        : "+f"((d)[0]),"+f"((d)[1]),"+f"((d)[2]),"+f"((d)[3])                   \
        : "r"((a)[0]),"r"((a)[1]),"r"((a)[2]),"r"((a)[3]),"r"(b0),"r"(b1))

__global__ __launch_bounds__(256, 2)
void conv_main_kernel(const float* __restrict__ feat,
                      const float* __restrict__ pred,
                      float* __restrict__ out) {
    __shared__ unsigned char s_rsel[128];

    const int tid = threadIdx.x;
    const int wid = tid >> 5, l = tid & 31;
    const int y = blockIdx.x, b = blockIdx.y;
    const unsigned smb = (unsigned)__cvta_generic_to_shared(dsm);

    // per-pixel r for this image row
    if (tid < 128) {
        float mn = 3.4e38f, mx = 0.f;
        #pragma unroll
        for (int i = 0; i < 16; ++i) {
            mn = fminf(mn, g_pmin[b*16 + i]);
            mx = fmaxf(mx, g_pmax[b*16 + i]);
        }
        int pix = b*HW + y*128 + tid;
        float sa = (g_sa[pix] - mn) / (mx - mn + 1e-8f);
        float pv = 1.f / (1.f + expf(-pred[pix]));
        s_rsel[tid] = (fmaxf(sa, pv) < 0.5f) ? 1 : 0;   // argmax([h,1-h])
    }

    const int warpM = wid >> 1, warpN = wid & 1;       // 4x2 warp grid
    const unsigned arow = (unsigned)((warpM*32 + (l & 15))*144 + ((l >> 4)*16));
    const unsigned brow = (unsigned)((warpN*64 + (l & 7) + ((l >> 4) << 3))*144
                                     + (((l >> 3) & 1)*16));
    const int kk2 = tid & 31, qq = tid >> 5;           // A-build mapping

    float acc[2][8][4];
    #pragma unroll
    for (int mt = 0; mt < 2; ++mt)
        #pragma unroll
        for (int nt = 0; nt < 8; ++nt)
            #pragma unroll
            for (int e = 0; e < 4; ++e) acc[mt][nt][e] = 0.f;

    // ---- staging helpers ----
    auto stage_fc = [&](int j, int buf) {   // fp32 halo cache, zero-filled OOB
        const int ci0 = (64*j) / 9;
        #pragma unroll 1
        for (int i = tid; i < 3168; i += 256) {
            int ci = i / 396, rem = i - ci*396;
            int row = rem / 132, xi = rem - row*132;
            int x = xi - 1, ry = y + row - 1;
            bool v = ((unsigned)x < 128u) & ((unsigned)ry < 128u);
            const float* src = feat + ((size_t)(b*CIN + ci0 + ci))*HW
                             + (v ? (ry*128 + x) : 0);
            asm volatile("cp.async.ca.shared.global [%0],[%1],4,%2;"
                         :: "r"(smb + FC_OFF + (unsigned)buf*FC_SZ + (unsigned)i*4u),
                            "l"(src), "r"(v ? 4 : 0));
        }
        asm volatile("cp.async.commit_group;");
    };
    auto stage_b = [&](int j) {             // B hi/lo into padded rows
        const unsigned char* slab = g_kbf + ((size_t)((b*9 + j)*2))*16384;
        #pragma unroll 1
        for (int i = tid; i < 2048; i += 256) {
            int split = i >> 10, rem = i & 1023;
            int n = rem >> 3, seg = rem & 7;
            const unsigned char* src = slab + (size_t)split*16384 + n*128 + seg*16;
            unsigned dst = smb + B_HI + (unsigned)split*18432u
                         + (unsigned)(n*144 + seg*16);
            asm volatile("cp.async.cg.shared.global [%0],[%1],16;"
                         :: "r"(dst), "l"(src));
        }
        asm volatile("cp.async.commit_group;");
    };

    stage_fc(0, 0);

    for (int j = 0; j < 9; ++j) {
        const int buf = j & 1;
        const int ci0 = (64*j) / 9;
        // fc_j complete (last committed group outstanding count 0 at loop top)
        asm volatile("cp.async.wait_group 0;");
        __syncthreads();   // fc visible; prev compute done -> A/B reusable

        stage_b(j);        // B_j in flight under A-build

        // ---- build A hi/lo (bf16 split, packed cvts, 32-bit stores) ----
        {
            const float* fc = (const float*)(dsm + FC_OFF + buf*FC_SZ);
            int K0 = 64*j + 2*kk2;
            int ciA = K0/9,     kA = K0 - 9*ciA;
            int ciB = (K0+1)/9, kB = (K0+1) - 9*ciB;
            int cA = (ciA - ci0)*396 + (kA/3)*132 + (kA % 3);
            int cB = (ciB - ci0)*396 + (kB/3)*132 + (kB % 3);
            #pragma unroll 4
            for (int pxi = 0; pxi < 16; ++pxi) {
                int px = qq*16 + pxi;
                float vA = fc[cA + px], vB = fc[cB + px];
                __nv_bfloat162 h2 = __floats2bfloat162_rn(vA, vB);
                uint32_t hbits = *(uint32_t*)&h2;
                float hAf = __uint_as_float(hbits << 16);
                float hBf = __uint_as_float(hbits & 0xFFFF0000u);
                __nv_bfloat162 l2 = __floats2bfloat162_rn(vA - hAf, vB - hBf);
                unsigned off = (unsigned)(px*144 + kk2*4);
                *(uint32_t*)(dsm + A_HI + off) = hbits;
                *(uint32_t*)(dsm + A_LO + off) = *(uint32_t*)&l2;
            }
        }

        if (j < 8) stage_fc(j + 1, buf ^ 1);   // prefetch under compute

        // wait for B_j (skip the in-flight fc group if present)
        if (j < 8) asm volatile("cp.async.wait_group 1;");
        else       asm volatile("cp.async.wait_group 0;");
        __syncthreads();   // A built + B visible to all warps

        // ---- compute: 4 k16-steps; passes ah*bh, al*bh, ah*bl ----
        #pragma unroll
        for (int ks = 0; ks < 4; ++ks) {
            const unsigned kb = (unsigned)ks*32u;
            uint32_t ah[2][4], al2[2][4];
            #pragma unroll
            for (int mt = 0; mt < 2; ++mt) {
                LDSM4(ah[mt][0],ah[mt][1],ah[mt][2],ah[mt][3],
                      smb + A_HI + arow + (unsigned)mt*2304u + kb);
                LDSM4(al2[mt][0],al2[mt][1],al2[mt][2],al2[mt][3],
                      smb + A_LO + arow + (unsigned)mt*2304u + kb);
            }
            #pragma unroll
            for (int half = 0; half < 2; ++half) {
                uint32_t bb[2][4];
                #pragma unroll
                for (int i = 0; i < 2; ++i)
                    LDSM4(bb[i][0],bb[i][1],bb[i][2],bb[i][3],
                          smb + B_HI + brow + (unsigned)(half*2 + i)*2304u + kb);
                #pragma unroll
                for (int mt = 0; mt < 2; ++mt)
                    #pragma unroll
                    for (int nt4 = 0; nt4 < 4; ++nt4) {
                        int nt = half*4 + nt4;
                        uint32_t b0 = bb[nt4 >> 1][(nt4 & 1)*2];
                        uint32_t b1 = bb[nt4 >> 1][(nt4 & 1)*2 + 1];
                        MMA(acc[mt][nt], ah[mt], b0, b1);
                        MMA(acc[mt][nt], al2[mt], b0, b1);
                    }
                #pragma unroll
                for (int i = 0; i < 2; ++i)
                    LDSM4(bb[i][0],bb[i][1],bb[i][2],bb[i][3],
                          smb + B_LO + brow + (unsigned)(half*2 + i)*2304u + kb);
                #pragma unroll
                for (int mt = 0; mt < 2; ++mt)
                    #pragma unroll
                    for (int nt4 = 0; nt4 < 4; ++nt4) {
                        int nt = half*4 + nt4;
                        uint32_t b0 = bb[nt4 >> 1][(nt4 & 1)*2];
                        uint32_t b1 = bb[nt4 >> 1][(nt4 & 1)*2 + 1];
                        MMA(acc[mt][nt], ah[mt], b0, b1);
                    }
            }
        }
    }

    // ---- epilogue: per-pixel r selection, direct register -> gmem ----
    const int pxw = warpM*32, nw = warpN*64;
    #pragma unroll
    for (int mt = 0; mt < 2; ++mt) {
        #pragma unroll
        for (int nt = 0; nt < 8; ++nt) {
            int n0 = nw + nt*8 + (l & 3)*2;
            int co = n0 & 63, rn = n0 >> 6;
            int px0 = pxw + mt*16 + (l >> 2);
            float* o = out + ((size_t)(b*COUT + co))*HW + y*128;
            if (s_rsel[px0] == rn) {
                o[px0]                = acc[mt][nt][0];
                o[(size_t)HW + px0]   = acc[mt][nt][1];
            }
            if (s_rsel[px0 + 8] == rn) {
                o[px0 + 8]              = acc[mt][nt][2];
                o[(size_t)HW + px0 + 8] = acc[mt][nt][3];
            }
        }
    }
}

// ---------------------------------------------------------------------------
// Launch: inputs in metadata order: feat, pred, w1, b1, w2, b2, gk
// ---------------------------------------------------------------------------
extern "C" void kernel_launch(void* const* d_in, const int* in_sizes, int n_in,
                              void* d_out, int out_size) {
    const float* feat = (const float*)d_in[0];
    const float* pred = (const float*)d_in[1];
    const float* w1   = (const float*)d_in[2];
    const float* b1   = (const float*)d_in[3];
    const float* w2   = (const float*)d_in[4];
    const float* b2   = (const float*)d_in[5];
    const float* gk   = (const float*)d_in[6];
    float* out = (float*)d_out;

    cudaFuncSetAttribute(conv_main_kernel,
                         cudaFuncAttributeMaxDynamicSharedMemorySize, CONV_DSMEM);

    poolsa_kernel<<<640, 256>>>(feat, pred, gk);
    kerngen_kernel<<<BB*2*9, 256>>>(w1, b1, w2, b2);

    dim3 gc(HH, BB);
    conv_main_kernel<<<gc, 256, CONV_DSMEM>>>(feat, pred, out);
}

// round 17
// speedup vs baseline: 1.4066x; 1.4066x over previous
#include <cuda_runtime.h>
#include <cuda_fp16.h>
#include <math.h>
#include <stdint.h>

#define BB   8
#define CIN  64
#define COUT 64
#define HH   128
#define WW   128
#define HID  8
#define HW   (HH*WW)

// ---------------------------------------------------------------------------
// Device scratch
// ---------------------------------------------------------------------------
__device__ float g_pooled[BB*CIN*9];
// fp16 B tiles for mma: slab = (b*9+j), layout [n=128][kk=64] fp16 (16384 B)
__device__ __align__(16) unsigned char g_kbf[(size_t)BB*9*16384];
__device__ float g_sa[BB*HW];
__device__ float g_pmin[BB*16];
__device__ float g_pmax[BB*16];

// ---------------------------------------------------------------------------
// 1) pool + sa (proven kernel, unchanged)
// ---------------------------------------------------------------------------
__global__ __launch_bounds__(256) void poolsa_kernel(const float* __restrict__ feat,
                                                     const float* __restrict__ pred,
                                                     const float* __restrict__ gk) {
    const int bid = blockIdx.x, tid = threadIdx.x;
    if (bid < 512) {
        __shared__ float red[9][256];
        const float* src = feat + (size_t)bid * HW;
        float a[9];
        #pragma unroll
        for (int i = 0; i < 9; ++i) a[i] = 0.f;
        for (int idx = tid; idx < HW; idx += 256) {
            float v = src[idx];
            int y = idx >> 7, x = idx & 127;
            bool rm0 = (y < 43), rm1 = (y >= 42) & (y < 86), rm2 = (y >= 85);
            bool cm0 = (x < 43), cm1 = (x >= 42) & (x < 86), cm2 = (x >= 85);
            if (rm0) { if (cm0) a[0]+=v; if (cm1) a[1]+=v; if (cm2) a[2]+=v; }
            if (rm1) { if (cm0) a[3]+=v; if (cm1) a[4]+=v; if (cm2) a[5]+=v; }
            if (rm2) { if (cm0) a[6]+=v; if (cm1) a[7]+=v; if (cm2) a[8]+=v; }
        }
        #pragma unroll
        for (int k = 0; k < 9; ++k) red[k][tid] = a[k];
        __syncthreads();
        for (int s = 128; s > 0; s >>= 1) {
            if (tid < s) {
                #pragma unroll
                for (int k = 0; k < 9; ++k) red[k][tid] += red[k][tid + s];
            }
            __syncthreads();
        }
        if (tid < 9) {
            const float cnt[3] = {43.f, 44.f, 43.f};
            g_pooled[bid*9 + tid] = red[tid][0] / (cnt[tid/3] * cnt[tid%3]);
        }
    } else {
        __shared__ float sp[46][46];
        __shared__ float sg[225];
        __shared__ float rmn[8], rmx[8];
        const int t = bid - 512, b = t >> 4, rem = t & 15;
        const int y0 = (rem >> 2) * 32, x0 = (rem & 3) * 32;
        for (int i = tid; i < 225; i += 256) sg[i] = gk[i];
        for (int i = tid; i < 46*46; i += 256) {
            int ly = i / 46, lx = i % 46;
            int gy = y0 - 7 + ly, gx = x0 - 7 + lx;
            float v = 0.f;
            if ((unsigned)gy < 128u && (unsigned)gx < 128u)
                v = 1.f / (1.f + expf(-pred[b*HW + gy*128 + gx]));
            sp[ly][lx] = v;
        }
        __syncthreads();
        float tmn = 3.4e38f, tmx = 0.f;
        #pragma unroll
        for (int p = 0; p < 4; ++p) {
            int id = tid + p*256, py = id >> 5, px = id & 31;
            float s = 0.f;
            for (int u = 0; u < 15; ++u)
                #pragma unroll
                for (int v = 0; v < 15; ++v)
                    s += sp[py + u][px + v] * sg[u*15 + v];
            g_sa[b*HW + (y0 + py)*128 + (x0 + px)] = s;
            tmn = fminf(tmn, s); tmx = fmaxf(tmx, s);
        }
        #pragma unroll
        for (int o = 16; o; o >>= 1) {
            tmn = fminf(tmn, __shfl_xor_sync(0xffffffffu, tmn, o));
            tmx = fmaxf(tmx, __shfl_xor_sync(0xffffffffu, tmx, o));
        }
        if ((tid & 31) == 0) { rmn[tid >> 5] = tmn; rmx[tid >> 5] = tmx; }
        __syncthreads();
        if (tid == 0) {
            #pragma unroll
            for (int w = 0; w < 8; ++w) { tmn = fminf(tmn, rmn[w]); tmx = fmaxf(tmx, rmx[w]); }
            g_pmin[b*16 + (y0 >> 5)*4 + (x0 >> 5)] = tmn;
            g_pmax[b*16 + (y0 >> 5)*4 + (x0 >> 5)] = tmx;
        }
    }
}

// ---------------------------------------------------------------------------
// 2) kerngen: MLP + emit fp16 B tiles [n=r*64+co][kk] per K-chunk slab
// ---------------------------------------------------------------------------
__global__ void kerngen_kernel(const float* __restrict__ w1,
                               const float* __restrict__ b1,
                               const float* __restrict__ w2,
                               const float* __restrict__ b2) {
    const int blk = blockIdx.x;               // 0..143 = (b, r, yx)
    const int b = blk / 18, rem = blk % 18;
    const int r = rem / 9, yx = rem % 9;
    __shared__ float hs[8];
    if (threadIdx.x < 8) {
        const int c = r*8 + threadIdx.x;
        float v = b1[c];
        #pragma unroll 8
        for (int ci = 0; ci < CIN; ++ci)
            v += w1[c*CIN + ci] * g_pooled[(b*CIN + ci)*9 + yx];
        hs[threadIdx.x] = 1.f / (1.f + expf(-v));
    }
    __syncthreads();
    for (int idx = threadIdx.x; idx < CIN*COUT; idx += 256) {
        const int co = idx & 63, ci = idx >> 6;
        const int q = r*(CIN*COUT) + co*CIN + ci;
        const float* wp = w2 + (size_t)q * HID;
        float v = b2[q];
        #pragma unroll
        for (int h = 0; h < HID; ++h) v += wp[h] * hs[h];
        __half hv = __float2half_rn(v);
        int K = ci*9 + yx, j = K >> 6, kk = K & 63;
        int n = r*64 + co;
        size_t base = ((size_t)(b*9 + j))*16384 + (size_t)n*128 + kk*2;
        *(unsigned short*)(g_kbf + base) = __half_as_ushort(hv);
    }
}

// ---------------------------------------------------------------------------
// 3) conv: mma.sync fp16 single-pass implicit GEMM, pipelined chunk loop.
//    Block=(y,b), 256 thr, 8 warps (4x2). D[128px,128n], K=576 in 9 chunks.
//    dsm: A[128][144B] fp16 | B[128][144B] fp16 | fc[2] fp32 [8][3][132]
// ---------------------------------------------------------------------------
#define A_OFF 0u
#define B_OFF 18432u
#define FC_OFF 36864u
#define FC_SZ  12672u
#define CONV_DSMEM 62208

extern __shared__ __align__(16) unsigned char dsm[];

#define LDSM4(r0,r1,r2,r3,a) \
    asm volatile("ldmatrix.sync.aligned.m8n8.x4.shared.b16 {%0,%1,%2,%3},[%4];" \
        : "=r"(r0),"=r"(r1),"=r"(r2),"=r"(r3) : "r"(a))

#define MMA(d, a, b0, b1)                                                       \
    asm volatile("mma.sync.aligned.m16n8k16.row.col.f32.f16.f16.f32 "           \
        "{%0,%1,%2,%3},{%4,%5,%6,%7},{%8,%9},{%0,%1,%2,%3};"                    \
        : "+f"((d)[0]),"+f"((d)[1]),"+f"((d)[2]),"+f"((d)[3])                   \
        : "r"((a)[0]),"r"((a)[1]),"r"((a)[2]),"r"((a)[3]),"r"(b0),"r"(b1))

__global__ __launch_bounds__(256, 2)
void conv_main_kernel(const float* __restrict__ feat,
                      const float* __restrict__ pred,
                      float* __restrict__ out) {
    __shared__ unsigned char s_rsel[128];

    const int tid = threadIdx.x;
    const int wid = tid >> 5, l = tid & 31;
    const int y = blockIdx.x, b = blockIdx.y;
    const unsigned smb = (unsigned)__cvta_generic_to_shared(dsm);

    // per-pixel r for this image row
    if (tid < 128) {
        float mn = 3.4e38f, mx = 0.f;
        #pragma unroll
        for (int i = 0; i < 16; ++i) {
            mn = fminf(mn, g_pmin[b*16 + i]);
            mx = fmaxf(mx, g_pmax[b*16 + i]);
        }
        int pix = b*HW + y*128 + tid;
        float sa = (g_sa[pix] - mn) / (mx - mn + 1e-8f);
        float pv = 1.f / (1.f + expf(-pred[pix]));
        s_rsel[tid] = (fmaxf(sa, pv) < 0.5f) ? 1 : 0;   // argmax([h,1-h])
    }

    const int warpM = wid >> 1, warpN = wid & 1;       // 4x2 warp grid
    const unsigned arow = (unsigned)((warpM*32 + (l & 15))*144 + ((l >> 4)*16));
    const unsigned brow = (unsigned)((warpN*64 + (l & 7) + ((l >> 4) << 3))*144
                                     + (((l >> 3) & 1)*16));
    const int kk2 = tid & 31, qq = tid >> 5;           // A-build mapping

    float acc[2][8][4];
    #pragma unroll
    for (int mt = 0; mt < 2; ++mt)
        #pragma unroll
        for (int nt = 0; nt < 8; ++nt)
            #pragma unroll
            for (int e = 0; e < 4; ++e) acc[mt][nt][e] = 0.f;

    // ---- staging helpers ----
    auto stage_fc = [&](int j, int buf) {   // fp32 halo cache, zero-filled OOB
        const int ci0 = (64*j) / 9;
        #pragma unroll 1
        for (int i = tid; i < 3168; i += 256) {
            int ci = i / 396, rem = i - ci*396;
            int row = rem / 132, xi = rem - row*132;
            int x = xi - 1, ry = y + row - 1;
            bool v = ((unsigned)x < 128u) & ((unsigned)ry < 128u);
            const float* src = feat + ((size_t)(b*CIN + ci0 + ci))*HW
                             + (v ? (ry*128 + x) : 0);
            asm volatile("cp.async.ca.shared.global [%0],[%1],4,%2;"
                         :: "r"(smb + FC_OFF + (unsigned)buf*FC_SZ + (unsigned)i*4u),
                            "l"(src), "r"(v ? 4 : 0));
        }
        asm volatile("cp.async.commit_group;");
    };
    auto stage_b = [&](int j) {             // fp16 B into padded rows
        const unsigned char* slab = g_kbf + ((size_t)(b*9 + j))*16384;
        #pragma unroll 1
        for (int i = tid; i < 1024; i += 256) {
            int n = i >> 3, seg = i & 7;
            const unsigned char* src = slab + n*128 + seg*16;
            unsigned dst = smb + B_OFF + (unsigned)(n*144 + seg*16);
            asm volatile("cp.async.cg.shared.global [%0],[%1],16;"
                         :: "r"(dst), "l"(src));
        }
        asm volatile("cp.async.commit_group;");
    };

    stage_fc(0, 0);

    for (int j = 0; j < 9; ++j) {
        const int buf = j & 1;
        const int ci0 = (64*j) / 9;
        asm volatile("cp.async.wait_group 0;");  // fc_j complete
        __syncthreads();   // fc visible; prev compute done -> A/B reusable

        stage_b(j);        // B_j in flight under A-build

        // ---- build A fp16 (packed cvt, 32-bit stores, conflict-free) ----
        {
            const float* fc = (const float*)(dsm + FC_OFF + buf*FC_SZ);
            int K0 = 64*j + 2*kk2;
            int ciA = K0/9,     kA = K0 - 9*ciA;
            int ciB = (K0+1)/9, kB = (K0+1) - 9*ciB;
            int cA = (ciA - ci0)*396 + (kA/3)*132 + (kA % 3);
            int cB = (ciB - ci0)*396 + (kB/3)*132 + (kB % 3);
            #pragma unroll 4
            for (int pxi = 0; pxi < 16; ++pxi) {
                int px = qq*16 + pxi;
                __half2 h2 = __floats2half2_rn(fc[cA + px], fc[cB + px]);
                unsigned off = (unsigned)(px*144 + kk2*4);
                *(uint32_t*)(dsm + A_OFF + off) = *(uint32_t*)&h2;
            }
        }

        if (j < 8) stage_fc(j + 1, buf ^ 1);   // prefetch under compute

        if (j < 8) asm volatile("cp.async.wait_group 1;");  // B_j done, fc in flight
        else       asm volatile("cp.async.wait_group 0;");
        __syncthreads();   // A built + B visible to all warps

        // ---- compute: 4 k16-steps, single fp16 pass ----
        #pragma unroll
        for (int ks = 0; ks < 4; ++ks) {
            const unsigned kb = (unsigned)ks*32u;
            uint32_t ah[2][4];
            #pragma unroll
            for (int mt = 0; mt < 2; ++mt)
                LDSM4(ah[mt][0],ah[mt][1],ah[mt][2],ah[mt][3],
                      smb + A_OFF + arow + (unsigned)mt*2304u + kb);
            #pragma unroll
            for (int half = 0; half < 2; ++half) {
                uint32_t bb[2][4];
                #pragma unroll
                for (int i = 0; i < 2; ++i)
                    LDSM4(bb[i][0],bb[i][1],bb[i][2],bb[i][3],
                          smb + B_OFF + brow + (unsigned)(half*2 + i)*2304u + kb);
                #pragma unroll
                for (int mt = 0; mt < 2; ++mt)
                    #pragma unroll
                    for (int nt4 = 0; nt4 < 4; ++nt4) {
                        int nt = half*4 + nt4;
                        uint32_t b0 = bb[nt4 >> 1][(nt4 & 1)*2];
                        uint32_t b1 = bb[nt4 >> 1][(nt4 & 1)*2 + 1];
                        MMA(acc[mt][nt], ah[mt], b0, b1);
                    }
            }
        }
    }

    // ---- epilogue: per-pixel r selection, direct register -> gmem ----
    const int pxw = warpM*32, nw = warpN*64;
    #pragma unroll
    for (int mt = 0; mt < 2; ++mt) {
        #pragma unroll
        for (int nt = 0; nt < 8; ++nt) {
            int n0 = nw + nt*8 + (l & 3)*2;
            int co = n0 & 63, rn = n0 >> 6;
            int px0 = pxw + mt*16 + (l >> 2);
            float* o = out + ((size_t)(b*COUT + co))*HW + y*128;
            if (s_rsel[px0] == rn) {
                o[px0]                = acc[mt][nt][0];
                o[(size_t)HW + px0]   = acc[mt][nt][1];
            }
            if (s_rsel[px0 + 8] == rn) {
                o[px0 + 8]              = acc[mt][nt][2];
                o[(size_t)HW + px0 + 8] = acc[mt][nt][3];
            }
        }
    }
}

// ---------------------------------------------------------------------------
// Launch: inputs in metadata order: feat, pred, w1, b1, w2, b2, gk
// ---------------------------------------------------------------------------
extern "C" void kernel_launch(void* const* d_in, const int* in_sizes, int n_in,
                              void* d_out, int out_size) {
    const float* feat = (const float*)d_in[0];
    const float* pred = (const float*)d_in[1];
    const float* w1   = (const float*)d_in[2];
    const float* b1   = (const float*)d_in[3];
    const float* w2   = (const float*)d_in[4];
    const float* b2   = (const float*)d_in[5];
    const float* gk   = (const float*)d_in[6];
    float* out = (float*)d_out;

    cudaFuncSetAttribute(conv_main_kernel,
                         cudaFuncAttributeMaxDynamicSharedMemorySize, CONV_DSMEM);

    poolsa_kernel<<<640, 256>>>(feat, pred, gk);
    kerngen_kernel<<<BB*2*9, 256>>>(w1, b1, w2, b2);

    dim3 gc(HH, BB);
    conv_main_kernel<<<gc, 256, CONV_DSMEM>>>(feat, pred, out);
}